// round 13
// baseline (speedup 1.0000x reference)
#include <cuda_runtime.h>
#include <cuda_bf16.h>
#include <cuda_fp16.h>
#include <math.h>

// Problem constants
#define NN 50000
#define EE 800000
#define ET 850000            // EE + NN self loops
#define HH 4
#define HC1 256
#define CC2 64
#define HC2 256
#define INF_ 128
#define NB 196               // ceil(NN/256)

// ---------------- scratch (device globals; no allocation) ----------------
__device__ __align__(16) __half g_h1[(size_t)NN * HC1];
__device__ __align__(16) __half g_h1a[(size_t)NN * HC1];
__device__ __align__(16) __half g_h2[(size_t)NN * HC2];
__device__ __align__(16) float  g_id[(size_t)NN * CC2];
__device__ __align__(16) float  g_asrc[NN * HH];
__device__ __align__(16) float  g_adst[NN * HH];
__device__ int   g_deg[NN];
__device__ int   g_row[NN + 1];
__device__ int   g_cursor[NN];
__device__ int   g_csr_src[ET];
__device__ int   g_bsum[NB];
__device__ int   g_boff[NB];
__device__ int   g_is64;

// ---------------- edge index dtype detection ----------------
__global__ void detect_kernel(const unsigned int* __restrict__ words) {
    __shared__ int any;
    if (threadIdx.x == 0) any = 0;
    __syncthreads();
    for (int i = threadIdx.x; i < 4096; i += blockDim.x)
        if (words[2 * i + 1] != 0u) any = 1;
    __syncthreads();
    if (threadIdx.x == 0) g_is64 = any ? 0 : 1;
}

__device__ __forceinline__ void load_edge(const void* ei, int e, int& src, int& dst) {
    if (e < EE) {
        if (g_is64) {
            const long long* p = (const long long*)ei;
            src = (int)p[e];
            dst = (int)p[EE + e];
        } else {
            const int* p = (const int*)ei;
            src = p[e];
            dst = p[EE + e];
        }
    } else {
        src = dst = e - EE;
    }
}

// ---------------- CSR build ----------------
__global__ void zero_deg_kernel() {
    int i = blockIdx.x * blockDim.x + threadIdx.x;
    if (i < NN) g_deg[i] = 0;
}

__global__ void count_kernel(const void* __restrict__ ei) {
    int e = blockIdx.x * blockDim.x + threadIdx.x;
    if (e >= ET) return;
    int s, d;
    load_edge(ei, e, s, d);
    atomicAdd(&g_deg[d], 1);
}

__global__ __launch_bounds__(256) void bsum_kernel() {
    __shared__ int sh[256];
    int i = blockIdx.x * 256 + threadIdx.x;
    sh[threadIdx.x] = (i < NN) ? g_deg[i] : 0;
    __syncthreads();
    for (int o = 128; o; o >>= 1) {
        if (threadIdx.x < o) sh[threadIdx.x] += sh[threadIdx.x + o];
        __syncthreads();
    }
    if (threadIdx.x == 0) g_bsum[blockIdx.x] = sh[0];
}

__global__ __launch_bounds__(256) void bscan_kernel() {
    __shared__ int sh[256];
    int tid = threadIdx.x;
    int v = (tid < NB) ? g_bsum[tid] : 0;
    sh[tid] = v;
    __syncthreads();
    for (int o = 1; o < 256; o <<= 1) {
        int t = 0;
        if (tid >= o) t = sh[tid - o];
        __syncthreads();
        sh[tid] += t;
        __syncthreads();
    }
    if (tid < NB) g_boff[tid] = sh[tid] - v;   // exclusive
    if (tid == 0) g_row[NN] = ET;
}

__global__ __launch_bounds__(256) void rowscan_kernel() {
    __shared__ int sh[256];
    int tid = threadIdx.x;
    int i = blockIdx.x * 256 + tid;
    int v = (i < NN) ? g_deg[i] : 0;
    sh[tid] = v;
    __syncthreads();
    for (int o = 1; o < 256; o <<= 1) {
        int t = 0;
        if (tid >= o) t = sh[tid - o];
        __syncthreads();
        sh[tid] += t;
        __syncthreads();
    }
    if (i < NN) {
        int r = g_boff[blockIdx.x] + sh[tid] - v;
        g_row[i] = r;
        g_cursor[i] = r;
    }
}

__global__ void fill_kernel(const void* __restrict__ ei) {
    int e = blockIdx.x * blockDim.x + threadIdx.x;
    if (e >= ET) return;
    int s, d;
    load_edge(ei, e, s, d);
    int pos = atomicAdd(&g_cursor[d], 1);
    g_csr_src[pos] = s;
}

// ---------------- tf32 helpers ----------------
__device__ __forceinline__ unsigned f2tf(float f) {
    unsigned r;
    asm("cvt.rna.tf32.f32 %0, %1;" : "=r"(r) : "f"(f));
    return r;
}

__device__ __forceinline__ void mma_tf32(
    float& c0, float& c1, float& c2, float& c3,
    unsigned a0, unsigned a1, unsigned a2, unsigned a3,
    unsigned b0, unsigned b1)
{
    asm volatile(
        "mma.sync.aligned.m16n8k8.row.col.f32.tf32.tf32.f32 "
        "{%0,%1,%2,%3}, {%4,%5,%6,%7}, {%8,%9}, {%0,%1,%2,%3};"
        : "+f"(c0), "+f"(c1), "+f"(c2), "+f"(c3)
        : "r"(a0), "r"(a1), "r"(a2), "r"(a3), "r"(b0), "r"(b1));
}

// ---------------- tf32 GEMM core (one output tile) ----------------
template<bool AHALF, bool CHALF>
__device__ __forceinline__ void gemm_tile(
    const void* __restrict__ Av, const float* __restrict__ B,
    const float* __restrict__ bias, void* __restrict__ Cv,
    int M, int Nc, int K, int bx, int by,
    unsigned (*As)[16][136], unsigned (*Bs)[16][136])
{
    const int t    = threadIdx.x;
    const int lane = t & 31;
    const int wid  = t >> 5;
    const int wm   = (wid & 3) * 32;
    const int wn   = (wid >> 2) * 64;
    const int tg   = lane & 3;
    const int gp   = lane >> 2;

    float c[2][8][4] = {};
    const int NIT = K >> 4;

    float4 aReg[2];
    uint4  aRegH;
    float4 bReg[2];

    auto ldA = [&](int k0) {
        if constexpr (AHALF) {
            const __half* A = (const __half*)Av;
            int row = t >> 1, kh = (t & 1) * 8;
            int gm = by + row;
            aRegH = make_uint4(0u, 0u, 0u, 0u);
            if (gm < M) aRegH = *(const uint4*)&A[(size_t)gm * K + k0 + kh];
        } else {
            const float* A = (const float*)Av;
            #pragma unroll
            for (int i = 0; i < 2; i++) {
                int idx = t + i * 256;
                int m = idx >> 2, cc = (idx & 3) * 4;
                int gm = by + m;
                aReg[i] = (gm < M) ? *(const float4*)&A[(size_t)gm * K + k0 + cc]
                                   : make_float4(0.f, 0.f, 0.f, 0.f);
            }
        }
    };
    auto ldB = [&](int k0) {
        #pragma unroll
        for (int i = 0; i < 2; i++) {
            int idx = t + i * 256;
            int kk = idx >> 5, n4 = idx & 31;
            int col = bx + n4 * 4;
            bReg[i] = (col < Nc) ? *(const float4*)&B[(size_t)(k0 + kk) * Nc + col]
                                 : make_float4(0.f, 0.f, 0.f, 0.f);
        }
    };
    auto stA = [&](int buf) {
        if constexpr (AHALF) {
            int row = t >> 1, kh = (t & 1) * 8;
            const __half2* hp = (const __half2*)&aRegH;
            #pragma unroll
            for (int j = 0; j < 4; j++) {
                float2 f = __half22float2(hp[j]);
                As[buf][kh + 2 * j][row]     = f2tf(f.x);
                As[buf][kh + 2 * j + 1][row] = f2tf(f.y);
            }
        } else {
            #pragma unroll
            for (int i = 0; i < 2; i++) {
                int idx = t + i * 256;
                int m = idx >> 2, cc = (idx & 3) * 4;
                As[buf][cc + 0][m] = f2tf(aReg[i].x);
                As[buf][cc + 1][m] = f2tf(aReg[i].y);
                As[buf][cc + 2][m] = f2tf(aReg[i].z);
                As[buf][cc + 3][m] = f2tf(aReg[i].w);
            }
        }
    };
    auto stB = [&](int buf) {
        #pragma unroll
        for (int i = 0; i < 2; i++) {
            int idx = t + i * 256;
            int kk = idx >> 5, n4 = idx & 31;
            Bs[buf][kk][n4 * 4 + 0] = f2tf(bReg[i].x);
            Bs[buf][kk][n4 * 4 + 1] = f2tf(bReg[i].y);
            Bs[buf][kk][n4 * 4 + 2] = f2tf(bReg[i].z);
            Bs[buf][kk][n4 * 4 + 3] = f2tf(bReg[i].w);
        }
    };

    ldA(0); ldB(0);
    stA(0); stB(0);

    int p = 0;
    for (int it = 0; it < NIT; it++) {
        __syncthreads();
        if (it + 1 < NIT) { ldA((it + 1) * 16); ldB((it + 1) * 16); }
        #pragma unroll
        for (int k8i = 0; k8i < 2; k8i++) {
            int kb = k8i * 8;
            unsigned a[2][4];
            #pragma unroll
            for (int mt = 0; mt < 2; mt++) {
                int m = wm + mt * 16 + gp;
                a[mt][0] = As[p][kb + tg][m];
                a[mt][1] = As[p][kb + tg][m + 8];
                a[mt][2] = As[p][kb + tg + 4][m];
                a[mt][3] = As[p][kb + tg + 4][m + 8];
            }
            #pragma unroll
            for (int nt = 0; nt < 8; nt++) {
                int n = wn + nt * 8 + gp;
                unsigned b0 = Bs[p][kb + tg][n];
                unsigned b1 = Bs[p][kb + tg + 4][n];
                #pragma unroll
                for (int mt = 0; mt < 2; mt++)
                    mma_tf32(c[mt][nt][0], c[mt][nt][1], c[mt][nt][2], c[mt][nt][3],
                             a[mt][0], a[mt][1], a[mt][2], a[mt][3], b0, b1);
            }
        }
        if (it + 1 < NIT) { int q = p ^ 1; stA(q); stB(q); }
        p ^= 1;
    }

    #pragma unroll
    for (int mt = 0; mt < 2; mt++) {
        int r0 = by + wm + mt * 16 + gp;
        #pragma unroll
        for (int nt = 0; nt < 8; nt++) {
            int col = bx + wn + nt * 8 + 2 * tg;
            if (col >= Nc) continue;
            if constexpr (CHALF) {
                __half* C = (__half*)Cv;
                if (r0 < M) {
                    __half2 h = __floats2half2_rn(c[mt][nt][0], c[mt][nt][1]);
                    *(__half2*)&C[(size_t)r0 * Nc + col] = h;
                }
                if (r0 + 8 < M) {
                    __half2 h = __floats2half2_rn(c[mt][nt][2], c[mt][nt][3]);
                    *(__half2*)&C[(size_t)(r0 + 8) * Nc + col] = h;
                }
            } else {
                float* C = (float*)Cv;
                float b0 = bias ? bias[col] : 0.f;
                float b1 = bias ? bias[col + 1] : 0.f;
                if (r0 < M)
                    *(float2*)&C[(size_t)r0 * Nc + col] =
                        make_float2(c[mt][nt][0] + b0, c[mt][nt][1] + b1);
                if (r0 + 8 < M)
                    *(float2*)&C[(size_t)(r0 + 8) * Nc + col] =
                        make_float2(c[mt][nt][2] + b0, c[mt][nt][3] + b1);
            }
        }
    }
}

// Fused layer-1 + residual GEMM
__global__ __launch_bounds__(256, 2) void gemm1_fused(
    const float* __restrict__ x, const float* __restrict__ W1,
    const float* __restrict__ Wres, const float* __restrict__ bres,
    __half* __restrict__ h1, float* __restrict__ idn)
{
    __shared__ unsigned As[2][16][136];
    __shared__ unsigned Bs[2][16][136];
    int by = blockIdx.y * 128;
    if (blockIdx.x < 2) {
        gemm_tile<false, true>(x, W1, nullptr, h1, NN, HC1, INF_,
                               blockIdx.x * 128, by, As, Bs);
    } else {
        gemm_tile<false, false>(x, Wres, bres, idn, NN, CC2, INF_,
                                0, by, As, Bs);
    }
}

__global__ __launch_bounds__(256, 2) void gemm2_kernel(
    const __half* __restrict__ h1a, const float* __restrict__ W2,
    __half* __restrict__ h2)
{
    __shared__ unsigned As[2][16][136];
    __shared__ unsigned Bs[2][16][136];
    gemm_tile<true, true>(h1a, W2, nullptr, h2, NN, HC2, HC1,
                          blockIdx.x * 128, blockIdx.y * 128, As, Bs);
}

// ---------------- alpha: 1 warp per node, all 4 heads ----------------
__global__ __launch_bounds__(256) void alpha_kernel(
    const __half* __restrict__ h, const float* __restrict__ att_s,
    const float* __restrict__ att_d, float* __restrict__ asrc,
    float* __restrict__ adst)
{
    int n = (blockIdx.x * blockDim.x + threadIdx.x) >> 5;
    int lane = threadIdx.x & 31;
    if (n >= NN) return;
    int off = lane * 8;
    uint4 raw = *(const uint4*)&h[(size_t)n * 256 + off];
    float4 a0 = *(const float4*)&att_s[off];
    float4 a1 = *(const float4*)&att_s[off + 4];
    float4 d0 = *(const float4*)&att_d[off];
    float4 d1 = *(const float4*)&att_d[off + 4];
    const __half2* hp = (const __half2*)&raw;
    float2 f0 = __half22float2(hp[0]);
    float2 f1 = __half22float2(hp[1]);
    float2 f2 = __half22float2(hp[2]);
    float2 f3 = __half22float2(hp[3]);
    float s1 = f0.x * a0.x + f0.y * a0.y + f1.x * a0.z + f1.y * a0.w
             + f2.x * a1.x + f2.y * a1.y + f3.x * a1.z + f3.y * a1.w;
    float s2 = f0.x * d0.x + f0.y * d0.y + f1.x * d0.z + f1.y * d0.w
             + f2.x * d1.x + f2.y * d1.y + f3.x * d1.z + f3.y * d1.w;
    #pragma unroll
    for (int o = 1; o < 8; o <<= 1) {
        s1 += __shfl_xor_sync(0xffffffffu, s1, o);
        s2 += __shfl_xor_sync(0xffffffffu, s2, o);
    }
    if ((lane & 7) == 0) {
        int hh = lane >> 3;
        asrc[n * 4 + hh] = s1;
        adst[n * 4 + hh] = s2;
    }
}

// ------- fused gather: inline softmax, predicated full-width tail -------
__device__ __forceinline__ void gather_node32f(
    int n, int lane, const __half* __restrict__ hfeat,
    const float* __restrict__ asrc, const float* __restrict__ adst,
    float acc[8])
{
    int r0 = g_row[n], deg = g_row[n + 1] - r0;
    int h = lane >> 3;
    float ad = __ldg(&adst[n * 4 + h]);
    const __half* fp = hfeat + lane * 8;
    #pragma unroll
    for (int i = 0; i < 8; i++) acc[i] = 0.f;
    float dsum = 0.f;
    for (int j = 0; j < deg; j += 8) {
        int s[8]; float wv[8]; uint4 raw[8];
        #pragma unroll
        for (int u = 0; u < 8; u++) {
            int idx = j + u < deg ? j + u : deg - 1;   // clamp
            s[u] = __ldg(&g_csr_src[r0 + idx]);
        }
        #pragma unroll
        for (int u = 0; u < 8; u++) {
            raw[u] = *(const uint4*)&fp[(size_t)s[u] * 256];
            float e = __ldg(&asrc[s[u] * 4 + h]) + ad;
            e = e > 0.f ? e : 0.2f * e;
            wv[u] = (j + u < deg) ? __expf(e) : 0.f;    // zero duplicate tail
        }
        #pragma unroll
        for (int u = 0; u < 8; u++) {
            dsum += wv[u];
            const __half2* hp = (const __half2*)&raw[u];
            #pragma unroll
            for (int k = 0; k < 4; k++) {
                float2 f = __half22float2(hp[k]);
                acc[2 * k]     = fmaf(wv[u], f.x, acc[2 * k]);
                acc[2 * k + 1] = fmaf(wv[u], f.y, acc[2 * k + 1]);
            }
        }
    }
    float sc = 1.f / dsum;
    #pragma unroll
    for (int i = 0; i < 8; i++) acc[i] *= sc;
}

// ---------------- layer 1: gather + bias + LN(256) + ELU -> fp16 ----------------
__global__ __launch_bounds__(256) void agg1_kernel(
    const __half* __restrict__ hfeat, const float* __restrict__ asrc,
    const float* __restrict__ adst, const float* __restrict__ bias,
    const float* __restrict__ g, const float* __restrict__ b,
    __half* __restrict__ out)
{
    int tid = threadIdx.x;
    int grp = tid >> 5, lane = tid & 31;
    int n = blockIdx.x * 8 + grp;

    float acc[8];
    gather_node32f(n, lane, hfeat, asrc, adst, acc);

    int off = lane * 8;
    float4 bv0 = *(const float4*)&bias[off];
    float4 bv1 = *(const float4*)&bias[off + 4];
    float v[8];
    v[0] = acc[0] + bv0.x; v[1] = acc[1] + bv0.y;
    v[2] = acc[2] + bv0.z; v[3] = acc[3] + bv0.w;
    v[4] = acc[4] + bv1.x; v[5] = acc[5] + bv1.y;
    v[6] = acc[6] + bv1.z; v[7] = acc[7] + bv1.w;

    float t = 0.f;
    #pragma unroll
    for (int i = 0; i < 8; i++) t += v[i];
    #pragma unroll
    for (int o = 16; o; o >>= 1) t += __shfl_xor_sync(0xffffffffu, t, o);
    float mu = t * (1.f / 256.f);
    float t2 = 0.f;
    #pragma unroll
    for (int i = 0; i < 8; i++) { float d = v[i] - mu; t2 += d * d; }
    #pragma unroll
    for (int o = 16; o; o >>= 1) t2 += __shfl_xor_sync(0xffffffffu, t2, o);
    float rs = rsqrtf(t2 * (1.f / 256.f) + 1e-5f);

    float4 gv0 = *(const float4*)&g[off];
    float4 gv1 = *(const float4*)&g[off + 4];
    float4 bb0 = *(const float4*)&b[off];
    float4 bb1 = *(const float4*)&b[off + 4];
    float gg[8] = {gv0.x, gv0.y, gv0.z, gv0.w, gv1.x, gv1.y, gv1.z, gv1.w};
    float bz[8] = {bb0.x, bb0.y, bb0.z, bb0.w, bb1.x, bb1.y, bb1.z, bb1.w};

    __half2 o4[4];
    #pragma unroll
    for (int k = 0; k < 4; k++) {
        float y0 = (v[2 * k] - mu) * rs * gg[2 * k] + bz[2 * k];
        float y1 = (v[2 * k + 1] - mu) * rs * gg[2 * k + 1] + bz[2 * k + 1];
        y0 = y0 > 0.f ? y0 : expm1f(y0);
        y1 = y1 > 0.f ? y1 : expm1f(y1);
        o4[k] = __floats2half2_rn(y0, y1);
    }
    *(uint4*)&out[(size_t)n * 256 + off] = *(uint4*)o4;
}

// ---------- layer 2: gather + head-mean + bias + LN(64) + res + ELU ----------
__global__ __launch_bounds__(256) void agg2_kernel(
    const __half* __restrict__ hfeat, const float* __restrict__ asrc,
    const float* __restrict__ adst, const float* __restrict__ bias,
    const float* __restrict__ g, const float* __restrict__ b,
    const float* __restrict__ idn, float* __restrict__ out)
{
    int tid = threadIdx.x;
    int grp = tid >> 5, lane = tid & 31;
    int n = blockIdx.x * 8 + grp;

    float acc[8];
    gather_node32f(n, lane, hfeat, asrc, adst, acc);

    int base = lane & 7;
    float m[8];
    #pragma unroll
    for (int i = 0; i < 8; i++) {
        float v0 = __shfl_sync(0xffffffffu, acc[i], base);
        float v1 = __shfl_sync(0xffffffffu, acc[i], base + 8);
        float v2 = __shfl_sync(0xffffffffu, acc[i], base + 16);
        float v3 = __shfl_sync(0xffffffffu, acc[i], base + 24);
        m[i] = 0.25f * (v0 + v1 + v2 + v3);
    }

    if (lane < 8) {
        int off = lane * 8;
        float4 bv0 = *(const float4*)&bias[off];
        float4 bv1 = *(const float4*)&bias[off + 4];
        float bvv[8] = {bv0.x, bv0.y, bv0.z, bv0.w, bv1.x, bv1.y, bv1.z, bv1.w};
        #pragma unroll
        for (int i = 0; i < 8; i++) m[i] += bvv[i];

        float t = 0.f;
        #pragma unroll
        for (int i = 0; i < 8; i++) t += m[i];
        #pragma unroll
        for (int o = 1; o < 8; o <<= 1) t += __shfl_xor_sync(0x000000ffu, t, o);
        float mu = t * (1.f / 64.f);
        float t2 = 0.f;
        #pragma unroll
        for (int i = 0; i < 8; i++) { float d = m[i] - mu; t2 += d * d; }
        #pragma unroll
        for (int o = 1; o < 8; o <<= 1) t2 += __shfl_xor_sync(0x000000ffu, t2, o);
        float rs = rsqrtf(t2 * (1.f / 64.f) + 1e-5f);

        float4 gv0 = *(const float4*)&g[off];
        float4 gv1 = *(const float4*)&g[off + 4];
        float4 bb0 = *(const float4*)&b[off];
        float4 bb1 = *(const float4*)&b[off + 4];
        float4 iv0 = *(const float4*)&idn[(size_t)n * 64 + off];
        float4 iv1 = *(const float4*)&idn[(size_t)n * 64 + off + 4];
        float gg[8] = {gv0.x, gv0.y, gv0.z, gv0.w, gv1.x, gv1.y, gv1.z, gv1.w};
        float bz[8] = {bb0.x, bb0.y, bb0.z, bb0.w, bb1.x, bb1.y, bb1.z, bb1.w};
        float iv[8] = {iv0.x, iv0.y, iv0.z, iv0.w, iv1.x, iv1.y, iv1.z, iv1.w};

        float y[8];
        #pragma unroll
        for (int i = 0; i < 8; i++) {
            float yy = (m[i] - mu) * rs * gg[i] + bz[i] + iv[i];
            y[i] = yy > 0.f ? yy : expm1f(yy);
        }
        *(float4*)&out[(size_t)n * 64 + off]     = make_float4(y[0], y[1], y[2], y[3]);
        *(float4*)&out[(size_t)n * 64 + off + 4] = make_float4(y[4], y[5], y[6], y[7]);
    }
}

// ---------------- launcher ----------------
extern "C" void kernel_launch(void* const* d_in, const int* in_sizes, int n_in,
                              void* d_out, int out_size) {
    const float* x        = (const float*)d_in[0];
    const void*  ei       = d_in[1];
    const float* W1       = (const float*)d_in[2];
    const float* att_src1 = (const float*)d_in[3];
    const float* att_dst1 = (const float*)d_in[4];
    const float* bias1    = (const float*)d_in[5];
    const float* g1       = (const float*)d_in[6];
    const float* b1       = (const float*)d_in[7];
    const float* W2       = (const float*)d_in[8];
    const float* att_src2 = (const float*)d_in[9];
    const float* att_dst2 = (const float*)d_in[10];
    const float* bias2    = (const float*)d_in[11];
    const float* g2       = (const float*)d_in[12];
    const float* b2       = (const float*)d_in[13];
    const float* Wres     = (const float*)d_in[14];
    const float* bres     = (const float*)d_in[15];
    float* out = (float*)d_out;

    __half *p_h1, *p_h1a, *p_h2;
    float *p_id, *p_asrc, *p_adst;
    cudaGetSymbolAddress((void**)&p_h1,   g_h1);
    cudaGetSymbolAddress((void**)&p_h1a,  g_h1a);
    cudaGetSymbolAddress((void**)&p_h2,   g_h2);
    cudaGetSymbolAddress((void**)&p_id,   g_id);
    cudaGetSymbolAddress((void**)&p_asrc, g_asrc);
    cudaGetSymbolAddress((void**)&p_adst, g_adst);

    // Side stream + events for CSR || GEMM1 overlap (host objects; created once).
    static cudaStream_t s2 = nullptr;
    static cudaEvent_t evFork = nullptr, evJoin = nullptr;
    if (!s2) {
        cudaStreamCreateWithFlags(&s2, cudaStreamNonBlocking);
        cudaEventCreateWithFlags(&evFork, cudaEventDisableTiming);
        cudaEventCreateWithFlags(&evJoin, cudaEventDisableTiming);
    }

    dim3 blk(256);

    // Fork: CSR build on s2, concurrent with GEMM1 + alpha1 on main stream.
    cudaEventRecord(evFork, 0);
    cudaStreamWaitEvent(s2, evFork, 0);

    detect_kernel<<<1, 256, 0, s2>>>((const unsigned int*)ei);
    zero_deg_kernel<<<NB, 256, 0, s2>>>();
    count_kernel<<<(ET + 255) / 256, 256, 0, s2>>>(ei);
    bsum_kernel<<<NB, 256, 0, s2>>>();
    bscan_kernel<<<1, 256, 0, s2>>>();
    rowscan_kernel<<<NB, 256, 0, s2>>>();
    fill_kernel<<<(ET + 255) / 256, 256, 0, s2>>>(ei);
    cudaEventRecord(evJoin, s2);

    // Main stream: fused layer-1 + residual projection, then alpha1.
    {
        dim3 grid(3, (NN + 127) / 128);
        gemm1_fused<<<grid, blk>>>(x, W1, Wres, bres, p_h1, p_id);
    }
    alpha_kernel<<<(NN * 32 + 255) / 256, 256>>>(p_h1, att_src1, att_dst1, p_asrc, p_adst);

    // Join: agg1 needs the CSR.
    cudaStreamWaitEvent(0, evJoin, 0);
    agg1_kernel<<<NN / 8, 256>>>(p_h1, p_asrc, p_adst, bias1, g1, b1, p_h1a);

    {
        dim3 grid(HC2 / 128, (NN + 127) / 128);
        gemm2_kernel<<<grid, blk>>>(p_h1a, W2, p_h2);
    }
    alpha_kernel<<<(NN * 32 + 255) / 256, 256>>>(p_h2, att_src2, att_dst2, p_asrc, p_adst);
    agg2_kernel<<<NN / 8, 256>>>(p_h2, p_asrc, p_adst, bias2, g2, b2, p_id, out);
}

// round 14
// speedup vs baseline: 1.0917x; 1.0917x over previous
#include <cuda_runtime.h>
#include <cuda_bf16.h>
#include <cuda_fp16.h>
#include <math.h>

// Problem constants
#define NN 50000
#define EE 800000
#define ET 850000            // EE + NN self loops
#define HH 4
#define HC1 256
#define CC2 64
#define HC2 256
#define INF_ 128
#define NB 196               // ceil(NN/256)

// ---------------- scratch (device globals; no allocation) ----------------
__device__ __align__(16) __half g_h1[(size_t)NN * HC1];
__device__ __align__(16) __half g_h1a[(size_t)NN * HC1];
__device__ __align__(16) __half g_h2[(size_t)NN * HC2];
__device__ __align__(16) float  g_id[(size_t)NN * CC2];
__device__ __align__(16) float  g_asrc[NN * HH];
__device__ __align__(16) float  g_adst[NN * HH];
__device__ int   g_deg[NN];
__device__ int   g_row[NN + 1];
__device__ int   g_cursor[NN];
__device__ int   g_csr_src[ET];
__device__ int   g_bsum[NB];
__device__ int   g_boff[NB];
__device__ int   g_is64;

// ---------------- edge index dtype detection ----------------
__global__ void detect_kernel(const unsigned int* __restrict__ words) {
    __shared__ int any;
    if (threadIdx.x == 0) any = 0;
    __syncthreads();
    for (int i = threadIdx.x; i < 4096; i += blockDim.x)
        if (words[2 * i + 1] != 0u) any = 1;
    __syncthreads();
    if (threadIdx.x == 0) g_is64 = any ? 0 : 1;
}

__device__ __forceinline__ void load_edge(const void* ei, int e, int& src, int& dst) {
    if (e < EE) {
        if (g_is64) {
            const long long* p = (const long long*)ei;
            src = (int)p[e];
            dst = (int)p[EE + e];
        } else {
            const int* p = (const int*)ei;
            src = p[e];
            dst = p[EE + e];
        }
    } else {
        src = dst = e - EE;
    }
}

// ---------------- CSR build ----------------
__global__ void zero_deg_kernel() {
    int i = blockIdx.x * blockDim.x + threadIdx.x;
    if (i < NN) g_deg[i] = 0;
}

__global__ void count_kernel(const void* __restrict__ ei) {
    int e = blockIdx.x * blockDim.x + threadIdx.x;
    if (e >= ET) return;
    int s, d;
    load_edge(ei, e, s, d);
    atomicAdd(&g_deg[d], 1);
}

__global__ __launch_bounds__(256) void bsum_kernel() {
    __shared__ int sh[256];
    int i = blockIdx.x * 256 + threadIdx.x;
    sh[threadIdx.x] = (i < NN) ? g_deg[i] : 0;
    __syncthreads();
    for (int o = 128; o; o >>= 1) {
        if (threadIdx.x < o) sh[threadIdx.x] += sh[threadIdx.x + o];
        __syncthreads();
    }
    if (threadIdx.x == 0) g_bsum[blockIdx.x] = sh[0];
}

__global__ __launch_bounds__(256) void bscan_kernel() {
    __shared__ int sh[256];
    int tid = threadIdx.x;
    int v = (tid < NB) ? g_bsum[tid] : 0;
    sh[tid] = v;
    __syncthreads();
    for (int o = 1; o < 256; o <<= 1) {
        int t = 0;
        if (tid >= o) t = sh[tid - o];
        __syncthreads();
        sh[tid] += t;
        __syncthreads();
    }
    if (tid < NB) g_boff[tid] = sh[tid] - v;   // exclusive
    if (tid == 0) g_row[NN] = ET;
}

__global__ __launch_bounds__(256) void rowscan_kernel() {
    __shared__ int sh[256];
    int tid = threadIdx.x;
    int i = blockIdx.x * 256 + tid;
    int v = (i < NN) ? g_deg[i] : 0;
    sh[tid] = v;
    __syncthreads();
    for (int o = 1; o < 256; o <<= 1) {
        int t = 0;
        if (tid >= o) t = sh[tid - o];
        __syncthreads();
        sh[tid] += t;
        __syncthreads();
    }
    if (i < NN) {
        int r = g_boff[blockIdx.x] + sh[tid] - v;
        g_row[i] = r;
        g_cursor[i] = r;
    }
}

__global__ void fill_kernel(const void* __restrict__ ei) {
    int e = blockIdx.x * blockDim.x + threadIdx.x;
    if (e >= ET) return;
    int s, d;
    load_edge(ei, e, s, d);
    int pos = atomicAdd(&g_cursor[d], 1);
    g_csr_src[pos] = s;
}

// ---------------- tf32 helpers ----------------
__device__ __forceinline__ unsigned f2tf(float f) {
    unsigned r;
    asm("cvt.rna.tf32.f32 %0, %1;" : "=r"(r) : "f"(f));
    return r;
}

__device__ __forceinline__ void mma_tf32(
    float& c0, float& c1, float& c2, float& c3,
    unsigned a0, unsigned a1, unsigned a2, unsigned a3,
    unsigned b0, unsigned b1)
{
    asm volatile(
        "mma.sync.aligned.m16n8k8.row.col.f32.tf32.tf32.f32 "
        "{%0,%1,%2,%3}, {%4,%5,%6,%7}, {%8,%9}, {%0,%1,%2,%3};"
        : "+f"(c0), "+f"(c1), "+f"(c2), "+f"(c3)
        : "r"(a0), "r"(a1), "r"(a2), "r"(a3), "r"(b0), "r"(b1));
}

// ---------------- tf32 GEMM core (one output tile) ----------------
template<bool AHALF, bool CHALF>
__device__ __forceinline__ void gemm_tile(
    const void* __restrict__ Av, const float* __restrict__ B,
    const float* __restrict__ bias, void* __restrict__ Cv,
    int M, int Nc, int K, int bx, int by,
    unsigned (*As)[16][136], unsigned (*Bs)[16][136])
{
    const int t    = threadIdx.x;
    const int lane = t & 31;
    const int wid  = t >> 5;
    const int wm   = (wid & 3) * 32;
    const int wn   = (wid >> 2) * 64;
    const int tg   = lane & 3;
    const int gp   = lane >> 2;

    float c[2][8][4] = {};
    const int NIT = K >> 4;

    float4 aReg[2];
    uint4  aRegH;
    float4 bReg[2];

    auto ldA = [&](int k0) {
        if constexpr (AHALF) {
            const __half* A = (const __half*)Av;
            int row = t >> 1, kh = (t & 1) * 8;
            int gm = by + row;
            aRegH = make_uint4(0u, 0u, 0u, 0u);
            if (gm < M) aRegH = *(const uint4*)&A[(size_t)gm * K + k0 + kh];
        } else {
            const float* A = (const float*)Av;
            #pragma unroll
            for (int i = 0; i < 2; i++) {
                int idx = t + i * 256;
                int m = idx >> 2, cc = (idx & 3) * 4;
                int gm = by + m;
                aReg[i] = (gm < M) ? *(const float4*)&A[(size_t)gm * K + k0 + cc]
                                   : make_float4(0.f, 0.f, 0.f, 0.f);
            }
        }
    };
    auto ldB = [&](int k0) {
        #pragma unroll
        for (int i = 0; i < 2; i++) {
            int idx = t + i * 256;
            int kk = idx >> 5, n4 = idx & 31;
            int col = bx + n4 * 4;
            bReg[i] = (col < Nc) ? *(const float4*)&B[(size_t)(k0 + kk) * Nc + col]
                                 : make_float4(0.f, 0.f, 0.f, 0.f);
        }
    };
    auto stA = [&](int buf) {
        if constexpr (AHALF) {
            int row = t >> 1, kh = (t & 1) * 8;
            const __half2* hp = (const __half2*)&aRegH;
            #pragma unroll
            for (int j = 0; j < 4; j++) {
                float2 f = __half22float2(hp[j]);
                As[buf][kh + 2 * j][row]     = f2tf(f.x);
                As[buf][kh + 2 * j + 1][row] = f2tf(f.y);
            }
        } else {
            #pragma unroll
            for (int i = 0; i < 2; i++) {
                int idx = t + i * 256;
                int m = idx >> 2, cc = (idx & 3) * 4;
                As[buf][cc + 0][m] = f2tf(aReg[i].x);
                As[buf][cc + 1][m] = f2tf(aReg[i].y);
                As[buf][cc + 2][m] = f2tf(aReg[i].z);
                As[buf][cc + 3][m] = f2tf(aReg[i].w);
            }
        }
    };
    auto stB = [&](int buf) {
        #pragma unroll
        for (int i = 0; i < 2; i++) {
            int idx = t + i * 256;
            int kk = idx >> 5, n4 = idx & 31;
            Bs[buf][kk][n4 * 4 + 0] = f2tf(bReg[i].x);
            Bs[buf][kk][n4 * 4 + 1] = f2tf(bReg[i].y);
            Bs[buf][kk][n4 * 4 + 2] = f2tf(bReg[i].z);
            Bs[buf][kk][n4 * 4 + 3] = f2tf(bReg[i].w);
        }
    };

    ldA(0); ldB(0);
    stA(0); stB(0);

    int p = 0;
    for (int it = 0; it < NIT; it++) {
        __syncthreads();
        if (it + 1 < NIT) { ldA((it + 1) * 16); ldB((it + 1) * 16); }
        #pragma unroll
        for (int k8i = 0; k8i < 2; k8i++) {
            int kb = k8i * 8;
            unsigned a[2][4];
            #pragma unroll
            for (int mt = 0; mt < 2; mt++) {
                int m = wm + mt * 16 + gp;
                a[mt][0] = As[p][kb + tg][m];
                a[mt][1] = As[p][kb + tg][m + 8];
                a[mt][2] = As[p][kb + tg + 4][m];
                a[mt][3] = As[p][kb + tg + 4][m + 8];
            }
            #pragma unroll
            for (int nt = 0; nt < 8; nt++) {
                int n = wn + nt * 8 + gp;
                unsigned b0 = Bs[p][kb + tg][n];
                unsigned b1 = Bs[p][kb + tg + 4][n];
                #pragma unroll
                for (int mt = 0; mt < 2; mt++)
                    mma_tf32(c[mt][nt][0], c[mt][nt][1], c[mt][nt][2], c[mt][nt][3],
                             a[mt][0], a[mt][1], a[mt][2], a[mt][3], b0, b1);
            }
        }
        if (it + 1 < NIT) { int q = p ^ 1; stA(q); stB(q); }
        p ^= 1;
    }

    #pragma unroll
    for (int mt = 0; mt < 2; mt++) {
        int r0 = by + wm + mt * 16 + gp;
        #pragma unroll
        for (int nt = 0; nt < 8; nt++) {
            int col = bx + wn + nt * 8 + 2 * tg;
            if (col >= Nc) continue;
            if constexpr (CHALF) {
                __half* C = (__half*)Cv;
                if (r0 < M) {
                    __half2 h = __floats2half2_rn(c[mt][nt][0], c[mt][nt][1]);
                    *(__half2*)&C[(size_t)r0 * Nc + col] = h;
                }
                if (r0 + 8 < M) {
                    __half2 h = __floats2half2_rn(c[mt][nt][2], c[mt][nt][3]);
                    *(__half2*)&C[(size_t)(r0 + 8) * Nc + col] = h;
                }
            } else {
                float* C = (float*)Cv;
                float b0 = bias ? bias[col] : 0.f;
                float b1 = bias ? bias[col + 1] : 0.f;
                if (r0 < M)
                    *(float2*)&C[(size_t)r0 * Nc + col] =
                        make_float2(c[mt][nt][0] + b0, c[mt][nt][1] + b1);
                if (r0 + 8 < M)
                    *(float2*)&C[(size_t)(r0 + 8) * Nc + col] =
                        make_float2(c[mt][nt][2] + b0, c[mt][nt][3] + b1);
            }
        }
    }
}

// Fused layer-1 + residual GEMM
__global__ __launch_bounds__(256, 2) void gemm1_fused(
    const float* __restrict__ x, const float* __restrict__ W1,
    const float* __restrict__ Wres, const float* __restrict__ bres,
    __half* __restrict__ h1, float* __restrict__ idn)
{
    __shared__ unsigned As[2][16][136];
    __shared__ unsigned Bs[2][16][136];
    int by = blockIdx.y * 128;
    if (blockIdx.x < 2) {
        gemm_tile<false, true>(x, W1, nullptr, h1, NN, HC1, INF_,
                               blockIdx.x * 128, by, As, Bs);
    } else {
        gemm_tile<false, false>(x, Wres, bres, idn, NN, CC2, INF_,
                                0, by, As, Bs);
    }
}

__global__ __launch_bounds__(256, 2) void gemm2_kernel(
    const __half* __restrict__ h1a, const float* __restrict__ W2,
    __half* __restrict__ h2)
{
    __shared__ unsigned As[2][16][136];
    __shared__ unsigned Bs[2][16][136];
    gemm_tile<true, true>(h1a, W2, nullptr, h2, NN, HC2, HC1,
                          blockIdx.x * 128, blockIdx.y * 128, As, Bs);
}

// ---------------- alpha: 1 warp per node, all 4 heads ----------------
__global__ __launch_bounds__(256) void alpha_kernel(
    const __half* __restrict__ h, const float* __restrict__ att_s,
    const float* __restrict__ att_d, float* __restrict__ asrc,
    float* __restrict__ adst)
{
    int n = (blockIdx.x * blockDim.x + threadIdx.x) >> 5;
    int lane = threadIdx.x & 31;
    if (n >= NN) return;
    int off = lane * 8;
    uint4 raw = *(const uint4*)&h[(size_t)n * 256 + off];
    float4 a0 = *(const float4*)&att_s[off];
    float4 a1 = *(const float4*)&att_s[off + 4];
    float4 d0 = *(const float4*)&att_d[off];
    float4 d1 = *(const float4*)&att_d[off + 4];
    const __half2* hp = (const __half2*)&raw;
    float2 f0 = __half22float2(hp[0]);
    float2 f1 = __half22float2(hp[1]);
    float2 f2 = __half22float2(hp[2]);
    float2 f3 = __half22float2(hp[3]);
    float s1 = f0.x * a0.x + f0.y * a0.y + f1.x * a0.z + f1.y * a0.w
             + f2.x * a1.x + f2.y * a1.y + f3.x * a1.z + f3.y * a1.w;
    float s2 = f0.x * d0.x + f0.y * d0.y + f1.x * d0.z + f1.y * d0.w
             + f2.x * d1.x + f2.y * d1.y + f3.x * d1.z + f3.y * d1.w;
    #pragma unroll
    for (int o = 1; o < 8; o <<= 1) {
        s1 += __shfl_xor_sync(0xffffffffu, s1, o);
        s2 += __shfl_xor_sync(0xffffffffu, s2, o);
    }
    if ((lane & 7) == 0) {
        int hh = lane >> 3;
        asrc[n * 4 + hh] = s1;
        adst[n * 4 + hh] = s2;
    }
}

// ------- fused gather: inline softmax, unroll 8 + scalar tail (R11 form) -------
__device__ __forceinline__ void gather_node32f(
    int n, int lane, const __half* __restrict__ hfeat,
    const float* __restrict__ asrc, const float* __restrict__ adst,
    float acc[8])
{
    int r0 = g_row[n], deg = g_row[n + 1] - r0;
    int h = lane >> 3;
    float ad = __ldg(&adst[n * 4 + h]);
    const __half* fp = hfeat + lane * 8;
    #pragma unroll
    for (int i = 0; i < 8; i++) acc[i] = 0.f;
    float dsum = 0.f;
    int j = 0;
    for (; j + 8 <= deg; j += 8) {
        int s[8]; float wv[8]; uint4 raw[8];
        #pragma unroll
        for (int u = 0; u < 8; u++)
            s[u] = __ldg(&g_csr_src[r0 + j + u]);
        #pragma unroll
        for (int u = 0; u < 8; u++) {
            raw[u] = *(const uint4*)&fp[(size_t)s[u] * 256];
            float e = __ldg(&asrc[s[u] * 4 + h]) + ad;
            e = e > 0.f ? e : 0.2f * e;
            wv[u] = __expf(e);
        }
        #pragma unroll
        for (int u = 0; u < 8; u++) {
            dsum += wv[u];
            const __half2* hp = (const __half2*)&raw[u];
            #pragma unroll
            for (int k = 0; k < 4; k++) {
                float2 f = __half22float2(hp[k]);
                acc[2 * k]     = fmaf(wv[u], f.x, acc[2 * k]);
                acc[2 * k + 1] = fmaf(wv[u], f.y, acc[2 * k + 1]);
            }
        }
    }
    for (; j < deg; j++) {
        int s = __ldg(&g_csr_src[r0 + j]);
        float e = __ldg(&asrc[s * 4 + h]) + ad;
        e = e > 0.f ? e : 0.2f * e;
        float wv = __expf(e);
        dsum += wv;
        uint4 raw = *(const uint4*)&fp[(size_t)s * 256];
        const __half2* hp = (const __half2*)&raw;
        #pragma unroll
        for (int k = 0; k < 4; k++) {
            float2 f = __half22float2(hp[k]);
            acc[2 * k]     = fmaf(wv, f.x, acc[2 * k]);
            acc[2 * k + 1] = fmaf(wv, f.y, acc[2 * k + 1]);
        }
    }
    float sc = 1.f / dsum;
    #pragma unroll
    for (int i = 0; i < 8; i++) acc[i] *= sc;
}

// ---------------- layer 1: gather + bias + LN(256) + ELU -> fp16 ----------------
__global__ __launch_bounds__(256) void agg1_kernel(
    const __half* __restrict__ hfeat, const float* __restrict__ asrc,
    const float* __restrict__ adst, const float* __restrict__ bias,
    const float* __restrict__ g, const float* __restrict__ b,
    __half* __restrict__ out)
{
    int tid = threadIdx.x;
    int grp = tid >> 5, lane = tid & 31;
    int n = blockIdx.x * 8 + grp;

    float acc[8];
    gather_node32f(n, lane, hfeat, asrc, adst, acc);

    int off = lane * 8;
    float4 bv0 = *(const float4*)&bias[off];
    float4 bv1 = *(const float4*)&bias[off + 4];
    float v[8];
    v[0] = acc[0] + bv0.x; v[1] = acc[1] + bv0.y;
    v[2] = acc[2] + bv0.z; v[3] = acc[3] + bv0.w;
    v[4] = acc[4] + bv1.x; v[5] = acc[5] + bv1.y;
    v[6] = acc[6] + bv1.z; v[7] = acc[7] + bv1.w;

    float t = 0.f;
    #pragma unroll
    for (int i = 0; i < 8; i++) t += v[i];
    #pragma unroll
    for (int o = 16; o; o >>= 1) t += __shfl_xor_sync(0xffffffffu, t, o);
    float mu = t * (1.f / 256.f);
    float t2 = 0.f;
    #pragma unroll
    for (int i = 0; i < 8; i++) { float d = v[i] - mu; t2 += d * d; }
    #pragma unroll
    for (int o = 16; o; o >>= 1) t2 += __shfl_xor_sync(0xffffffffu, t2, o);
    float rs = rsqrtf(t2 * (1.f / 256.f) + 1e-5f);

    float4 gv0 = *(const float4*)&g[off];
    float4 gv1 = *(const float4*)&g[off + 4];
    float4 bb0 = *(const float4*)&b[off];
    float4 bb1 = *(const float4*)&b[off + 4];
    float gg[8] = {gv0.x, gv0.y, gv0.z, gv0.w, gv1.x, gv1.y, gv1.z, gv1.w};
    float bz[8] = {bb0.x, bb0.y, bb0.z, bb0.w, bb1.x, bb1.y, bb1.z, bb1.w};

    __half2 o4[4];
    #pragma unroll
    for (int k = 0; k < 4; k++) {
        float y0 = (v[2 * k] - mu) * rs * gg[2 * k] + bz[2 * k];
        float y1 = (v[2 * k + 1] - mu) * rs * gg[2 * k + 1] + bz[2 * k + 1];
        y0 = y0 > 0.f ? y0 : expm1f(y0);
        y1 = y1 > 0.f ? y1 : expm1f(y1);
        o4[k] = __floats2half2_rn(y0, y1);
    }
    *(uint4*)&out[(size_t)n * 256 + off] = *(uint4*)o4;
}

// ---------- layer 2: gather + head-mean + bias + LN(64) + res + ELU ----------
__global__ __launch_bounds__(256) void agg2_kernel(
    const __half* __restrict__ hfeat, const float* __restrict__ asrc,
    const float* __restrict__ adst, const float* __restrict__ bias,
    const float* __restrict__ g, const float* __restrict__ b,
    const float* __restrict__ idn, float* __restrict__ out)
{
    int tid = threadIdx.x;
    int grp = tid >> 5, lane = tid & 31;
    int n = blockIdx.x * 8 + grp;

    float acc[8];
    gather_node32f(n, lane, hfeat, asrc, adst, acc);

    int base = lane & 7;
    float m[8];
    #pragma unroll
    for (int i = 0; i < 8; i++) {
        float v0 = __shfl_sync(0xffffffffu, acc[i], base);
        float v1 = __shfl_sync(0xffffffffu, acc[i], base + 8);
        float v2 = __shfl_sync(0xffffffffu, acc[i], base + 16);
        float v3 = __shfl_sync(0xffffffffu, acc[i], base + 24);
        m[i] = 0.25f * (v0 + v1 + v2 + v3);
    }

    if (lane < 8) {
        int off = lane * 8;
        float4 bv0 = *(const float4*)&bias[off];
        float4 bv1 = *(const float4*)&bias[off + 4];
        float bvv[8] = {bv0.x, bv0.y, bv0.z, bv0.w, bv1.x, bv1.y, bv1.z, bv1.w};
        #pragma unroll
        for (int i = 0; i < 8; i++) m[i] += bvv[i];

        float t = 0.f;
        #pragma unroll
        for (int i = 0; i < 8; i++) t += m[i];
        #pragma unroll
        for (int o = 1; o < 8; o <<= 1) t += __shfl_xor_sync(0x000000ffu, t, o);
        float mu = t * (1.f / 64.f);
        float t2 = 0.f;
        #pragma unroll
        for (int i = 0; i < 8; i++) { float d = m[i] - mu; t2 += d * d; }
        #pragma unroll
        for (int o = 1; o < 8; o <<= 1) t2 += __shfl_xor_sync(0x000000ffu, t2, o);
        float rs = rsqrtf(t2 * (1.f / 64.f) + 1e-5f);

        float4 gv0 = *(const float4*)&g[off];
        float4 gv1 = *(const float4*)&g[off + 4];
        float4 bb0 = *(const float4*)&b[off];
        float4 bb1 = *(const float4*)&b[off + 4];
        float4 iv0 = *(const float4*)&idn[(size_t)n * 64 + off];
        float4 iv1 = *(const float4*)&idn[(size_t)n * 64 + off + 4];
        float gg[8] = {gv0.x, gv0.y, gv0.z, gv0.w, gv1.x, gv1.y, gv1.z, gv1.w};
        float bz[8] = {bb0.x, bb0.y, bb0.z, bb0.w, bb1.x, bb1.y, bb1.z, bb1.w};
        float iv[8] = {iv0.x, iv0.y, iv0.z, iv0.w, iv1.x, iv1.y, iv1.z, iv1.w};

        float y[8];
        #pragma unroll
        for (int i = 0; i < 8; i++) {
            float yy = (m[i] - mu) * rs * gg[i] + bz[i] + iv[i];
            y[i] = yy > 0.f ? yy : expm1f(yy);
        }
        *(float4*)&out[(size_t)n * 64 + off]     = make_float4(y[0], y[1], y[2], y[3]);
        *(float4*)&out[(size_t)n * 64 + off + 4] = make_float4(y[4], y[5], y[6], y[7]);
    }
}

// ---------------- launcher ----------------
extern "C" void kernel_launch(void* const* d_in, const int* in_sizes, int n_in,
                              void* d_out, int out_size) {
    const float* x        = (const float*)d_in[0];
    const void*  ei       = d_in[1];
    const float* W1       = (const float*)d_in[2];
    const float* att_src1 = (const float*)d_in[3];
    const float* att_dst1 = (const float*)d_in[4];
    const float* bias1    = (const float*)d_in[5];
    const float* g1       = (const float*)d_in[6];
    const float* b1       = (const float*)d_in[7];
    const float* W2       = (const float*)d_in[8];
    const float* att_src2 = (const float*)d_in[9];
    const float* att_dst2 = (const float*)d_in[10];
    const float* bias2    = (const float*)d_in[11];
    const float* g2       = (const float*)d_in[12];
    const float* b2       = (const float*)d_in[13];
    const float* Wres     = (const float*)d_in[14];
    const float* bres     = (const float*)d_in[15];
    float* out = (float*)d_out;

    __half *p_h1, *p_h1a, *p_h2;
    float *p_id, *p_asrc, *p_adst;
    cudaGetSymbolAddress((void**)&p_h1,   g_h1);
    cudaGetSymbolAddress((void**)&p_h1a,  g_h1a);
    cudaGetSymbolAddress((void**)&p_h2,   g_h2);
    cudaGetSymbolAddress((void**)&p_id,   g_id);
    cudaGetSymbolAddress((void**)&p_asrc, g_asrc);
    cudaGetSymbolAddress((void**)&p_adst, g_adst);

    // Side stream + events for CSR || GEMM1 overlap (host objects; created once).
    static cudaStream_t s2 = nullptr;
    static cudaEvent_t evFork = nullptr, evJoin = nullptr;
    if (!s2) {
        cudaStreamCreateWithFlags(&s2, cudaStreamNonBlocking);
        cudaEventCreateWithFlags(&evFork, cudaEventDisableTiming);
        cudaEventCreateWithFlags(&evJoin, cudaEventDisableTiming);
    }

    dim3 blk(256);

    // Fork: CSR build on s2, concurrent with GEMM1 + alpha1 on main stream.
    cudaEventRecord(evFork, 0);
    cudaStreamWaitEvent(s2, evFork, 0);

    detect_kernel<<<1, 256, 0, s2>>>((const unsigned int*)ei);
    zero_deg_kernel<<<NB, 256, 0, s2>>>();
    count_kernel<<<(ET + 255) / 256, 256, 0, s2>>>(ei);
    bsum_kernel<<<NB, 256, 0, s2>>>();
    bscan_kernel<<<1, 256, 0, s2>>>();
    rowscan_kernel<<<NB, 256, 0, s2>>>();
    fill_kernel<<<(ET + 255) / 256, 256, 0, s2>>>(ei);
    cudaEventRecord(evJoin, s2);

    // Main stream: fused layer-1 + residual projection, then alpha1.
    {
        dim3 grid(3, (NN + 127) / 128);
        gemm1_fused<<<grid, blk>>>(x, W1, Wres, bres, p_h1, p_id);
    }
    alpha_kernel<<<(NN * 32 + 255) / 256, 256>>>(p_h1, att_src1, att_dst1, p_asrc, p_adst);

    // Join: agg1 needs the CSR.
    cudaStreamWaitEvent(0, evJoin, 0);
    agg1_kernel<<<NN / 8, 256>>>(p_h1, p_asrc, p_adst, bias1, g1, b1, p_h1a);

    {
        dim3 grid(HC2 / 128, (NN + 127) / 128);
        gemm2_kernel<<<grid, blk>>>(p_h1a, W2, p_h2);
    }
    alpha_kernel<<<(NN * 32 + 255) / 256, 256>>>(p_h2, att_src2, att_dst2, p_asrc, p_adst);
    agg2_kernel<<<NN / 8, 256>>>(p_h2, p_asrc, p_adst, bias2, g2, b2, p_id, out);
}